// round 14
// baseline (speedup 1.0000x reference)
#include <cuda_runtime.h>

#define EPSF 1e-9f
#define FMINN 1.17549435e-38f
#define TOPKK 13
#define MAXB 8
#define MAXN 50
#define MAXL 8400
#define MAXK 17
#define CH   25      // gts per K1 z-chunk
#define NCH  2
#define CAPC 2048    // per-gt candidate list capacity (geometric bound ~400)

extern "C" __device__ float __nv_expf(float);
extern "C" __device__ float __nv_powf(float, float);

// ---------------- device scratch ----------------
__device__ unsigned int       g_gts[NCH][MAXB*MAXL];
__device__ unsigned long long g_topk[MAXB*MAXL];
__device__ float g_cmaxv[NCH][MAXB*MAXL];
__device__ short g_cmaxi[NCH][MAXB*MAXL];
__device__ short         g_coln[MAXB*MAXL];
__device__ unsigned char g_pos [MAXB*MAXL];
__device__ float g_alout[MAXB*MAXL];        // align at (asg, l) for positives
__device__ float g_maxm[MAXB*MAXN];
__device__ float g_maxi[MAXB*MAXN];
__device__ int   g_ccnt[MAXB*MAXN];
__device__ float g_cv[MAXB*MAXN*CAPC];
__device__ int   g_cl[MAXB*MAXN*CAPC];
// K0 per-(b,n[,k]) precompute
__device__ float4 g_kp4 [MAXB*MAXN*MAXK];   // gx, gy, screen-thresh, vis
__device__ float  g_aeps[MAXB*MAXN];
__device__ float  g_areac[MAXB*MAXN];
__device__ float  g_nvise[MAXB*MAXN];

__device__ __forceinline__ float ftz(float x) { return (x < FMINN) ? 0.f : x; }

// Exact pair metric (identical intrinsic sequence everywhere -> bit-identical)
__device__ __forceinline__ void pair_metrics(
    const float* __restrict__ ps, const float* __restrict__ pb,
    const float* __restrict__ pp, int C, int L, int b, int lg,
    float4 g4, float areac, float aeps, float nvise, int lab,
    const float4* kp4, const float* s2,
    float& io2_out, float& al_out)
{
    float4 p = ((const float4*)pb)[(long)b*L + lg];
    float area_p = __fmul_rn(fmaxf(__fsub_rn(p.z, p.x), 0.f),
                             fmaxf(__fsub_rn(p.w, p.y), 0.f));
    float ox = __fsub_rn(fminf(g4.z, p.z), fmaxf(g4.x, p.x));
    float oy = __fsub_rn(fminf(g4.w, p.w), fmaxf(g4.y, p.y));
    float ov = __fmul_rn(fmaxf(ox, 0.f), fmaxf(oy, 0.f));
    io2_out = 0.f; al_out = 0.f;
    if (ov > 0.f) {
        float den = __fadd_rn(__fsub_rn(__fadd_rn(areac, area_p), ov), EPSF);
        float iou = __fdiv_rn(ov, den);
        const float2* pr = (const float2*)(pp + ((long)(b*L + lg))*MAXK*2);
        float s = 0.f;
        #pragma unroll
        for (int k = 0; k < MAXK; k++) {
            float4 kk = kp4[k];
            if (kk.w > 0.f) {
                float2 q2 = pr[k];
                float dx = __fsub_rn(kk.x, q2.x);
                float dy = __fsub_rn(kk.y, q2.y);
                float d  = __fadd_rn(__fmul_rn(dx, dx), __fmul_rn(dy, dy));
                if (d <= kk.z) {
                    float e2 = __fdiv_rn(__fdiv_rn(__fdiv_rn(d, s2[k]), aeps), 2.0f);
                    s = __fadd_rn(s, ftz(__nv_expf(-e2)));
                }
            }
        }
        float oks = ftz(__fdiv_rn(s, nvise));
        float io2 = ftz(__fmul_rn(iou, oks));
        float p6  = ftz(__nv_powf(io2, 6.0f));
        al_out  = ftz(__fmul_rn(ps[(long)(b*L + lg)*C + lab], p6));
        io2_out = io2;
    }
}

// ============================================================
// K0: per-gt setup + resets
// ============================================================
__global__ void __launch_bounds__(256)
k0_setup(const float* __restrict__ gb, const float* __restrict__ gp,
         const float* __restrict__ sg, int B, int N, int K)
{
    __shared__ float s_s2[MAXK];
    __shared__ float s_aeps[MAXN];
    const int b = blockIdx.x, tid = threadIdx.x;

    if (tid < K) { float t = __fmul_rn(2.0f, sg[tid]); s_s2[tid] = __fmul_rn(t, t); }
    if (tid < N) {
        int n = tid;
        g_ccnt[b*N + n] = 0;
        g_maxm[b*N + n] = 0.f;
        g_maxi[b*N + n] = 0.f;
        const float* bx = gb + (b*N + n)*4;
        float wg = __fsub_rn(bx[2], bx[0]), hg = __fsub_rn(bx[3], bx[1]);
        g_areac[b*N + n] = __fmul_rn(fmaxf(wg, 0.f), fmaxf(hg, 0.f));
        float ae = __fadd_rn(__fmul_rn(__fmul_rn(wg, hg), 0.53f), EPSF);
        s_aeps[n] = ae; g_aeps[b*N + n] = ae;
        float c = 0.f;
        for (int k = 0; k < K; k++) {
            float v = gp[((long)(b*N + n)*K + k)*3 + 2];
            c = __fadd_rn(c, (v > 0.f) ? 1.f : 0.f);
        }
        g_nvise[b*N + n] = __fadd_rn(c, EPSF);
    }
    __syncthreads();
    for (int j = tid; j < N*K; j += blockDim.x) {
        int n = j / K, k = j - n*K;
        const float* g = gp + ((long)(b*N + n)*K + k)*3;
        // d > th  =>  e > 87.9  =>  exp term < min-normal => flushed to 0
        double th = (double)s_s2[k] * (double)s_aeps[n] * 2.0 * 87.9;
        g_kp4[(b*N + n)*K + k] = make_float4(g[0], g[1], (float)th, (g[2] > 0.f) ? 1.f : 0.f);
    }
}

// ============================================================
// K1: phase A (cheap screen) -> smem pair queue -> phase B
//     (full-efficiency heavy math; candidates + chunk argmax only)
// ============================================================
__global__ void __launch_bounds__(256)
k1_metrics(const float* __restrict__ ps, const float* __restrict__ pb,
           const float* __restrict__ pp, const float* __restrict__ ap,
           const int*   __restrict__ glab, const float* __restrict__ gb,
           const float* __restrict__ sg,
           int B, int L, int C, int N, int K)
{
    __shared__ float4 s_box[CH];
    __shared__ float4 s_kp [CH*MAXK];
    __shared__ float  s_aeps[CH], s_areac[CH], s_nvise[CH];
    __shared__ int    s_lab[CH];
    __shared__ float  s_s2[MAXK];
    __shared__ unsigned int s_bits[256];
    __shared__ unsigned long long s_amax[256];
    __shared__ unsigned int s_q[CH*256];
    __shared__ int s_qc;

    const int b = blockIdx.y, z = blockIdx.z, tid = threadIdx.x;
    const int c0 = z*CH;
    const int cn = min(N, c0 + CH) - c0;

    if (tid == 0) s_qc = 0;
    if (tid < K) { float t = __fmul_rn(2.0f, sg[tid]); s_s2[tid] = __fmul_rn(t, t); }
    if (tid < cn) {
        int n = c0 + tid;
        s_box[tid]   = ((const float4*)gb)[b*N + n];
        s_aeps[tid]  = g_aeps[b*N + n];
        s_areac[tid] = g_areac[b*N + n];
        s_nvise[tid] = g_nvise[b*N + n];
        s_lab[tid]   = glab[b*N + n];
    }
    for (int j = tid; j < cn*K; j += blockDim.x)
        s_kp[j] = g_kp4[(b*N + c0)*K + j];
    __syncthreads();

    const int l = blockIdx.x*blockDim.x + tid;
    const bool active = (l < L);

    if (active) {
        float4 p = ((const float4*)pb)[b*L + l];
        float axx = ap[l*2], ayy = ap[l*2 + 1];
        unsigned int bits = 0;
        for (int j = 0; j < cn; j++) {
            float4 g4 = s_box[j];
            float ox = __fsub_rn(fminf(g4.z, p.z), fmaxf(g4.x, p.x));
            float oy = __fsub_rn(fminf(g4.w, p.w), fmaxf(g4.y, p.y));
            float ov = __fmul_rn(fmaxf(ox, 0.f), fmaxf(oy, 0.f));
            float dmin = fminf(fminf(__fsub_rn(axx, g4.x), __fsub_rn(ayy, g4.y)),
                               fminf(__fsub_rn(g4.z, axx), __fsub_rn(g4.w, ayy)));
            if (dmin > EPSF) bits |= (1u << j);
            if (ov > 0.f) {
                int qp = atomicAdd(&s_qc, 1);
                s_q[qp] = ((unsigned)tid << 5) | (unsigned)j;
            }
        }
        s_bits[tid] = bits;
        // argmax init: io2 = 0 at n = c0 (first occurrence over all-zero chunk)
        s_amax[tid] = (unsigned long long)(unsigned)(N - c0);
        g_gts[z][b*L + l] = bits;
        if (z == 0) g_topk[b*L + l] = 0ull;
    }
    __syncthreads();

    const int qc = s_qc;
    for (int q = tid; q < qc; q += 256) {
        unsigned e = s_q[q];
        int ll = (int)(e >> 5), j = (int)(e & 31);
        int lg = blockIdx.x*256 + ll;
        int n  = c0 + j;
        float io2, al;
        pair_metrics(ps, pb, pp, C, L, b, lg,
                     s_box[j], s_areac[j], s_aeps[j], s_nvise[j], s_lab[j],
                     &s_kp[j*MAXK], s_s2, io2, al);
        unsigned long long key =
            ((unsigned long long)__float_as_uint(io2) << 32) | (unsigned)(N - n);
        atomicMax(&s_amax[ll], key);
        if (al > 0.f && ((s_bits[ll] >> j) & 1u)) {
            int id = atomicAdd(&g_ccnt[b*N + n], 1);
            if (id < CAPC) {
                g_cv[(b*N + n)*CAPC + id] = al;
                g_cl[(b*N + n)*CAPC + id] = lg;
            }
        }
    }
    __syncthreads();

    if (active) {
        unsigned long long key = s_amax[tid];
        g_cmaxv[z][b*L + l] = __uint_as_float((unsigned)(key >> 32));
        g_cmaxi[z][b*L + l] = (short)(N - (int)(key & 0xffffffffull));
    }
}

// ============================================================
// K2: top-13 per (b,n) from candidate lists
//     (candidates desc by value, idx asc; then lowest-index zero fill)
// ============================================================
__global__ void __launch_bounds__(256)
k2_topk(const float* __restrict__ pad, int B, int L, int N)
{
    __shared__ float cv[CAPC];
    __shared__ int   ci[CAPC];
    __shared__ float rv[256];
    __shared__ int   ri[256];
    __shared__ int   rp[256];

    const int n = blockIdx.x, b = blockIdx.y, tid = threadIdx.x;
    if (pad[b*N + n] <= 0.f) return;

    const int cnt = min(g_ccnt[b*N + n], CAPC);
    const unsigned long long nb = 1ull << n;

    for (int i = tid; i < cnt; i += 256) {
        cv[i] = g_cv[(b*N + n)*CAPC + i];
        ci[i] = g_cl[(b*N + n)*CAPC + i];
    }
    __syncthreads();

    if (cnt <= TOPKK) {
        if (tid < cnt) atomicOr(&g_topk[(long)b*L + ci[tid]], nb);
        if (tid == 0) {
            int fill = TOPKK - cnt;
            for (int i = 0; fill > 0; i++) {
                bool cand = false;
                for (int j = 0; j < cnt; j++) if (ci[j] == i) { cand = true; break; }
                if (!cand) { atomicOr(&g_topk[(long)b*L + i], nb); fill--; }
            }
        }
    } else {
        for (int t = 0; t < TOPKK; t++) {
            float bv = -1.f; int ba = 0x7fffffff; int bp = -1;
            for (int i = tid; i < cnt; i += 256) {
                float v = cv[i]; int a = ci[i];
                if (v > bv || (v == bv && a < ba)) { bv = v; ba = a; bp = i; }
            }
            rv[tid] = bv; ri[tid] = ba; rp[tid] = bp;
            __syncthreads();
            for (int off = 128; off > 0; off >>= 1) {
                if (tid < off) {
                    float v2 = rv[tid+off]; int a2 = ri[tid+off];
                    if (v2 > rv[tid] || (v2 == rv[tid] && a2 < ri[tid])) {
                        rv[tid] = v2; ri[tid] = a2; rp[tid] = rp[tid+off];
                    }
                }
                __syncthreads();
            }
            if (tid == 0) { atomicOr(&g_topk[(long)b*L + ri[0]], nb); cv[rp[0]] = -1.f; }
            __syncthreads();
        }
    }
}

// ============================================================
// K3: per-anchor resolve + exact recompute at (asg, l) for positives
// ============================================================
__global__ void __launch_bounds__(128)
k3_resolve(const float* __restrict__ ps, const float* __restrict__ pb,
           const float* __restrict__ pp, const int* __restrict__ glab,
           const float* __restrict__ gb, const float* __restrict__ sg,
           int B, int L, int C, int N, int K)
{
    __shared__ float s_s2[MAXK];
    const int tid = threadIdx.x;
    if (tid < K) { float t = __fmul_rn(2.0f, sg[tid]); s_s2[tid] = __fmul_rn(t, t); }
    __syncthreads();

    const int l = blockIdx.x*blockDim.x + tid;
    const int b = blockIdx.y;
    if (l >= L) return;
    const int bl = b*L + l;

    unsigned long long gts = (unsigned long long)g_gts[0][bl]
                           | ((unsigned long long)g_gts[1][bl] << CH);
    unsigned long long pos64 = gts & g_topk[bl];
    int cnt = __popcll(pos64);

    int asg = 0, pos = 0;
    if (cnt == 1) { asg = __ffsll((long long)pos64) - 1; pos = 1; }
    else if (cnt > 1) {             // global iou argmax, first-occurrence ties
        float v0 = g_cmaxv[0][bl], v1 = g_cmaxv[1][bl];
        asg = (v1 > v0) ? (int)g_cmaxi[1][bl] : (int)g_cmaxi[0][bl];
        pos = 1;
    }
    g_coln[bl] = (short)asg;
    g_pos [bl] = (unsigned char)pos;

    float al = 0.f;
    if (pos) {
        const int gn = b*N + asg;
        float io2;
        pair_metrics(ps, pb, pp, C, L, b, l,
                     ((const float4*)gb)[gn], g_areac[gn], g_aeps[gn],
                     g_nvise[gn], glab[gn], &g_kp4[gn*MAXK], s_s2, io2, al);
        atomicMax((int*)&g_maxm[gn], __float_as_int(al));
        atomicMax((int*)&g_maxi[gn], __float_as_int(io2));
    }
    g_alout[bl] = al;
}

// ============================================================
// K56: fused outputs
// layout: [labels BL][bboxes 4BL][poses 3K*BL][scores C*BL][gtidx BL][crowd BL]
// ============================================================
__global__ void __launch_bounds__(256)
k56_out(float* __restrict__ out,
        const int* __restrict__ glab, const float* __restrict__ gb,
        const int* __restrict__ gcrowd, const int* __restrict__ bgp,
        const float* __restrict__ gp,
        int B, int L, int C, int N, int K)
{
    __shared__ int    s_lab[MAXN], s_crowd[MAXN];
    __shared__ float4 s_box[MAXN];
    __shared__ float  s_mm[MAXN], s_mi[MAXN];
    __shared__ float  s_gp[MAXN*MAXK*3];

    const int b = blockIdx.y, tid = threadIdx.x;
    const int K3 = K*3;
    if (tid < N) {
        s_lab[tid]   = glab[b*N + tid];
        s_crowd[tid] = gcrowd[b*N + tid];
        s_box[tid]   = ((const float4*)gb)[b*N + tid];
        s_mm[tid]    = g_maxm[b*N + tid];
        s_mi[tid]    = g_maxi[b*N + tid];
    }
    for (int j = tid; j < N*K3; j += 256) s_gp[j] = gp[(long)b*N*K3 + j];
    __syncthreads();

    const int l = blockIdx.x*blockDim.x + tid;
    if (l >= L) return;
    const int bg = bgp ? bgp[0] : 1;

    const int n     = g_coln[b*L + l];
    const int pos   = g_pos [b*L + l];
    const int crowd = s_crowd[n];

    const int lab_pre = pos ? s_lab[n] : bg;
    const int lab_fin = (crowd > 0) ? bg : lab_pre;

    float mult = 0.f;
    if (pos)
        mult = __fmul_rn(__fdiv_rn(g_alout[b*L + l], __fadd_rn(s_mm[n], EPSF)), s_mi[n]);
    const float cf = (crowd < 1) ? 1.f : 0.f;

    const long BL = (long)B*L;
    const long o  = (long)b*L + l;

    out[o] = (float)lab_fin;
    ((float4*)(out + BL))[o] = s_box[n];

    float* pout = out + BL*5 + (long)b*L*K3 + (long)l*K3;
    const float* src = s_gp + n*K3;
    #pragma unroll
    for (int j = 0; j < MAXK*3; j++) pout[j] = src[j];

    const long off_sc = BL*5 + BL*(long)K*3;
    for (int cc = 0; cc < C; cc++) {
        int kept = (cc < bg) ? cc : cc + 1;
        out[off_sc + o*C + cc] = __fmul_rn((lab_pre == kept) ? mult : 0.f, cf);
    }
    const long off_gi = off_sc + BL*(long)C;
    out[off_gi + o]      = (float)(n + b*N);
    out[off_gi + BL + o] = (crowd > 0) ? 1.f : 0.f;
}

// ============================================================
extern "C" void kernel_launch(void* const* d_in, const int* in_sizes, int n_in,
                              void* d_out, int out_size)
{
    const float* ps   = (const float*)d_in[0];
    const float* pb   = (const float*)d_in[1];
    const float* pp   = (const float*)d_in[2];
    const float* ap   = (const float*)d_in[3];
    const int*   glab = (const int*)  d_in[4];
    const float* gb   = (const float*)d_in[5];
    const float* gp   = (const float*)d_in[6];
    const int*   gc   = (const int*)  d_in[7];
    const float* pad  = (const float*)d_in[8];
    const float* sg   = (const float*)d_in[9];
    const int*   bgp  = (n_in > 10) ? (const int*)d_in[10] : nullptr;

    const int K  = in_sizes[9];
    const int L  = in_sizes[3] / 2;
    const int BL = in_sizes[1] / 4;
    const int B  = BL / L;
    const int C  = in_sizes[0] / BL;
    const int N  = in_sizes[4] / B;

    dim3 blk(256);
    const int gx = (L + 255)/256;
    k0_setup  <<<B, blk>>>(gb, gp, sg, B, N, K);
    k1_metrics<<<dim3(gx, B, NCH), blk>>>(ps, pb, pp, ap, glab, gb, sg, B, L, C, N, K);
    k2_topk   <<<dim3(N, B), blk>>>(pad, B, L, N);
    k3_resolve<<<dim3((L + 127)/128, B), dim3(128)>>>(ps, pb, pp, glab, gb, sg, B, L, C, N, K);
    k56_out   <<<dim3(gx, B), blk>>>((float*)d_out, glab, gb, gc, bgp, gp, B, L, C, N, K);
    (void)out_size;
}

// round 15
// speedup vs baseline: 1.3913x; 1.3913x over previous
#include <cuda_runtime.h>

#define EPSF 1e-9f
#define FMINN 1.17549435e-38f
#define TOPKK 13
#define MAXB 8
#define MAXN 50
#define MAXL 8400
#define MAXK 17
#define CH   25      // gts per K1 z-chunk
#define NCH  2
#define CAPC 2048    // per-gt candidate list capacity (geometric bound ~400)

extern "C" __device__ float __nv_expf(float);
extern "C" __device__ float __nv_powf(float, float);

// ---------------- device scratch ----------------
__device__ float g_align[MAXB*MAXN*MAXL];
__device__ float g_iou  [MAXB*MAXN*MAXL];
__device__ unsigned int       g_gts[NCH][MAXB*MAXL];
__device__ unsigned long long g_topk[MAXB*MAXL];
__device__ float g_cmaxv[NCH][MAXB*MAXL];
__device__ short g_cmaxi[NCH][MAXB*MAXL];
__device__ short         g_coln[MAXB*MAXL];
__device__ unsigned char g_pos [MAXB*MAXL];
__device__ float g_maxm[MAXB*MAXN];
__device__ float g_maxi[MAXB*MAXN];
__device__ int   g_ccnt[MAXB*MAXN];
__device__ float g_cv[MAXB*MAXN*CAPC];
__device__ int   g_cl[MAXB*MAXN*CAPC];
// K0 per-(b,n[,k]) precompute
__device__ float4 g_kp4 [MAXB*MAXN*MAXK];   // gx, gy, screen-thresh, vis
__device__ float  g_aeps[MAXB*MAXN];
__device__ float  g_areac[MAXB*MAXN];
__device__ float  g_nvise[MAXB*MAXN];

__device__ __forceinline__ float ftz(float x) { return (x < FMINN) ? 0.f : x; }

// ============================================================
// K0: per-gt setup + resets
// ============================================================
__global__ void __launch_bounds__(256)
k0_setup(const float* __restrict__ gb, const float* __restrict__ gp,
         const float* __restrict__ sg, int B, int N, int K)
{
    __shared__ float s_s2[MAXK];
    __shared__ float s_aeps[MAXN];
    const int b = blockIdx.x, tid = threadIdx.x;

    if (tid < K) { float t = __fmul_rn(2.0f, sg[tid]); s_s2[tid] = __fmul_rn(t, t); }
    if (tid < N) {
        int n = tid;
        g_ccnt[b*N + n] = 0;
        g_maxm[b*N + n] = 0.f;
        g_maxi[b*N + n] = 0.f;
        const float* bx = gb + (b*N + n)*4;
        float wg = __fsub_rn(bx[2], bx[0]), hg = __fsub_rn(bx[3], bx[1]);
        g_areac[b*N + n] = __fmul_rn(fmaxf(wg, 0.f), fmaxf(hg, 0.f));
        float ae = __fadd_rn(__fmul_rn(__fmul_rn(wg, hg), 0.53f), EPSF);
        s_aeps[n] = ae; g_aeps[b*N + n] = ae;
        float c = 0.f;
        for (int k = 0; k < K; k++) {
            float v = gp[((long)(b*N + n)*K + k)*3 + 2];
            c = __fadd_rn(c, (v > 0.f) ? 1.f : 0.f);
        }
        g_nvise[b*N + n] = __fadd_rn(c, EPSF);
    }
    __syncthreads();
    for (int j = tid; j < N*K; j += blockDim.x) {
        int n = j / K, k = j - n*K;
        const float* g = gp + ((long)(b*N + n)*K + k)*3;
        // d > th  =>  e > 87.9  =>  exp term < min-normal => flushed to 0
        double th = (double)s_s2[k] * (double)s_aeps[n] * 2.0 * 87.9;
        g_kp4[(b*N + n)*K + k] = make_float4(g[0], g[1], (float)th, (g[2] > 0.f) ? 1.f : 0.f);
    }
}

// ============================================================
// K1: phase A (cheap screen + dense zero fill) -> smem pair queue
//     -> phase B (full-efficiency heavy math) ; FTZ pipeline
// ============================================================
__global__ void __launch_bounds__(256)
k1_metrics(const float* __restrict__ ps, const float* __restrict__ pb,
           const float* __restrict__ pp, const float* __restrict__ ap,
           const int*   __restrict__ glab, const float* __restrict__ gb,
           const float* __restrict__ sg,
           int B, int L, int C, int N, int K)
{
    __shared__ float4 s_box[CH];
    __shared__ float4 s_kp [CH*MAXK];
    __shared__ float  s_aeps[CH], s_areac[CH], s_nvise[CH];
    __shared__ int    s_lab[CH];
    __shared__ float  s_s2[MAXK];
    __shared__ unsigned int s_bits[256];
    __shared__ unsigned long long s_amax[256];
    __shared__ unsigned int s_q[CH*256];
    __shared__ int s_qc;

    const int b = blockIdx.y, z = blockIdx.z, tid = threadIdx.x;
    const int c0 = z*CH;
    const int cn = min(N, c0 + CH) - c0;

    if (tid == 0) s_qc = 0;
    if (tid < K) { float t = __fmul_rn(2.0f, sg[tid]); s_s2[tid] = __fmul_rn(t, t); }
    if (tid < cn) {
        int n = c0 + tid;
        s_box[tid]   = ((const float4*)gb)[b*N + n];
        s_aeps[tid]  = g_aeps[b*N + n];
        s_areac[tid] = g_areac[b*N + n];
        s_nvise[tid] = g_nvise[b*N + n];
        s_lab[tid]   = glab[b*N + n];
    }
    for (int j = tid; j < cn*K; j += blockDim.x)
        s_kp[j] = g_kp4[(b*N + c0)*K + j];
    __syncthreads();

    const int l = blockIdx.x*blockDim.x + tid;
    const bool active = (l < L);

    if (active) {
        float4 p = ((const float4*)pb)[b*L + l];
        float axx = ap[l*2], ayy = ap[l*2 + 1];
        unsigned int bits = 0;
        for (int j = 0; j < cn; j++) {
            float4 g4 = s_box[j];
            float ox = __fsub_rn(fminf(g4.z, p.z), fmaxf(g4.x, p.x));
            float oy = __fsub_rn(fminf(g4.w, p.w), fmaxf(g4.y, p.y));
            float ov = __fmul_rn(fmaxf(ox, 0.f), fmaxf(oy, 0.f));
            float dmin = fminf(fminf(__fsub_rn(axx, g4.x), __fsub_rn(ayy, g4.y)),
                               fminf(__fsub_rn(g4.z, axx), __fsub_rn(g4.w, ayy)));
            long idx = ((long)(b*N + c0 + j))*L + l;
            g_iou[idx]   = 0.f;
            g_align[idx] = 0.f;
            if (dmin > EPSF) bits |= (1u << j);
            if (ov > 0.f) {
                int qp = atomicAdd(&s_qc, 1);
                s_q[qp] = ((unsigned)tid << 5) | (unsigned)j;
            }
        }
        s_bits[tid] = bits;
        // argmax init: io2 = 0 at n = c0 (first occurrence over all-zero chunk)
        s_amax[tid] = (unsigned long long)(unsigned)(N - c0);
        g_gts[z][b*L + l] = bits;
        if (z == 0) g_topk[b*L + l] = 0ull;
    }
    __syncthreads();

    const int qc = s_qc;
    for (int q = tid; q < qc; q += 256) {
        unsigned e = s_q[q];
        int ll = (int)(e >> 5), j = (int)(e & 31);
        int lg = blockIdx.x*256 + ll;
        int n  = c0 + j;
        float4 p = ((const float4*)pb)[b*L + lg];
        float area_p = __fmul_rn(fmaxf(__fsub_rn(p.z, p.x), 0.f),
                                 fmaxf(__fsub_rn(p.w, p.y), 0.f));
        float4 g4 = s_box[j];
        float ox = __fsub_rn(fminf(g4.z, p.z), fmaxf(g4.x, p.x));
        float oy = __fsub_rn(fminf(g4.w, p.w), fmaxf(g4.y, p.y));
        float ov = __fmul_rn(fmaxf(ox, 0.f), fmaxf(oy, 0.f));
        float den = __fadd_rn(__fsub_rn(__fadd_rn(s_areac[j], area_p), ov), EPSF);
        float iou = __fdiv_rn(ov, den);
        float aeps = s_aeps[j];
        const float2* pr = (const float2*)(pp + ((long)(b*L + lg))*MAXK*2);
        float s = 0.f;
        #pragma unroll
        for (int k = 0; k < MAXK; k++) {
            float4 kk = s_kp[j*MAXK + k];
            if (kk.w > 0.f) {
                float2 q2 = pr[k];
                float dx = __fsub_rn(kk.x, q2.x);
                float dy = __fsub_rn(kk.y, q2.y);
                float d  = __fadd_rn(__fmul_rn(dx, dx), __fmul_rn(dy, dy));
                if (d <= kk.z) {
                    float e2 = __fdiv_rn(__fdiv_rn(__fdiv_rn(d, s_s2[k]), aeps), 2.0f);
                    s = __fadd_rn(s, ftz(__nv_expf(-e2)));
                }
            }
        }
        float oks = ftz(__fdiv_rn(s, s_nvise[j]));
        float io2 = ftz(__fmul_rn(iou, oks));
        float p6  = ftz(__nv_powf(io2, 6.0f));
        float al  = ftz(__fmul_rn(ps[(long)(b*L + lg)*C + s_lab[j]], p6));

        long idx = ((long)(b*N + n))*L + lg;
        g_iou[idx]   = io2;
        g_align[idx] = al;
        unsigned long long key =
            ((unsigned long long)__float_as_uint(io2) << 32) | (unsigned)(N - n);
        atomicMax(&s_amax[ll], key);
        if (al > 0.f && ((s_bits[ll] >> j) & 1u)) {
            int id = atomicAdd(&g_ccnt[b*N + n], 1);
            if (id < CAPC) {
                g_cv[(b*N + n)*CAPC + id] = al;
                g_cl[(b*N + n)*CAPC + id] = lg;
            }
        }
    }
    __syncthreads();

    if (active) {
        unsigned long long key = s_amax[tid];
        g_cmaxv[z][b*L + l] = __uint_as_float((unsigned)(key >> 32));
        g_cmaxi[z][b*L + l] = (short)(N - (int)(key & 0xffffffffull));
    }
}

// ============================================================
// K2: top-13 per (b,n) from candidate lists
//     (value desc, index asc; then lowest-index zero fill)
// ============================================================
__global__ void __launch_bounds__(256)
k2_topk(const float* __restrict__ pad, int B, int L, int N)
{
    __shared__ float cv[CAPC];
    __shared__ int   ci[CAPC];
    __shared__ float rv[256];
    __shared__ int   ri[256];
    __shared__ int   rp[256];

    const int n = blockIdx.x, b = blockIdx.y, tid = threadIdx.x;
    if (pad[b*N + n] <= 0.f) return;

    const int cnt = min(g_ccnt[b*N + n], CAPC);
    const unsigned long long nb = 1ull << n;

    for (int i = tid; i < cnt; i += 256) {
        cv[i] = g_cv[(b*N + n)*CAPC + i];
        ci[i] = g_cl[(b*N + n)*CAPC + i];
    }
    __syncthreads();

    if (cnt <= TOPKK) {
        if (tid < cnt) atomicOr(&g_topk[(long)b*L + ci[tid]], nb);
        if (tid == 0) {
            int fill = TOPKK - cnt;
            for (int i = 0; fill > 0; i++) {
                bool cand = false;
                for (int j = 0; j < cnt; j++) if (ci[j] == i) { cand = true; break; }
                if (!cand) { atomicOr(&g_topk[(long)b*L + i], nb); fill--; }
            }
        }
    } else {
        for (int t = 0; t < TOPKK; t++) {
            float bv = -1.f; int ba = 0x7fffffff; int bp = -1;
            for (int i = tid; i < cnt; i += 256) {
                float v = cv[i]; int a = ci[i];
                if (v > bv || (v == bv && a < ba)) { bv = v; ba = a; bp = i; }
            }
            rv[tid] = bv; ri[tid] = ba; rp[tid] = bp;
            __syncthreads();
            for (int off = 128; off > 0; off >>= 1) {
                if (tid < off) {
                    float v2 = rv[tid+off]; int a2 = ri[tid+off];
                    if (v2 > rv[tid] || (v2 == rv[tid] && a2 < ri[tid])) {
                        rv[tid] = v2; ri[tid] = a2; rp[tid] = rp[tid+off];
                    }
                }
                __syncthreads();
            }
            if (tid == 0) { atomicOr(&g_topk[(long)b*L + ri[0]], nb); cv[rp[0]] = -1.f; }
            __syncthreads();
        }
    }
}

// ============================================================
// K3: per-anchor resolve — bit ops + 2-way chunk-argmax combine,
//     dense reads only at positives
// ============================================================
__global__ void __launch_bounds__(256)
k3_resolve(int B, int L, int N)
{
    const int l = blockIdx.x*blockDim.x + threadIdx.x;
    const int b = blockIdx.y;
    if (l >= L) return;
    const int bl = b*L + l;

    unsigned long long gts = (unsigned long long)g_gts[0][bl]
                           | ((unsigned long long)g_gts[1][bl] << CH);
    unsigned long long pos64 = gts & g_topk[bl];
    int cnt = __popcll(pos64);

    int asg = 0, pos = 0;
    if (cnt == 1) { asg = __ffsll((long long)pos64) - 1; pos = 1; }
    else if (cnt > 1) {
        float v0 = g_cmaxv[0][bl], v1 = g_cmaxv[1][bl];
        asg = (v1 > v0) ? (int)g_cmaxi[1][bl] : (int)g_cmaxi[0][bl];
        pos = 1;
    }
    g_coln[bl] = (short)asg;
    g_pos [bl] = (unsigned char)pos;
    if (pos) {
        long idx = ((long)(b*N + asg))*L + l;
        atomicMax((int*)&g_maxm[b*N + asg], __float_as_int(g_align[idx]));
        atomicMax((int*)&g_maxi[b*N + asg], __float_as_int(g_iou[idx]));
    }
}

// ============================================================
// K56: fused outputs — coalesced pose copy via smem coln staging
// layout: [labels BL][bboxes 4BL][poses 3K*BL][scores C*BL][gtidx BL][crowd BL]
// ============================================================
__global__ void __launch_bounds__(256)
k56_out(float* __restrict__ out,
        const int* __restrict__ glab, const float* __restrict__ gb,
        const int* __restrict__ gcrowd, const int* __restrict__ bgp,
        const float* __restrict__ gp,
        int B, int L, int C, int N, int K)
{
    __shared__ int    s_lab[MAXN], s_crowd[MAXN];
    __shared__ float4 s_box[MAXN];
    __shared__ float  s_mm[MAXN], s_mi[MAXN];
    __shared__ float  s_gp[MAXN*MAXK*3];
    __shared__ short  s_cl[256];

    const int b = blockIdx.y, tid = threadIdx.x;
    const int K3 = K*3;
    const int l0 = blockIdx.x*256;

    if (tid < N) {
        s_lab[tid]   = glab[b*N + tid];
        s_crowd[tid] = gcrowd[b*N + tid];
        s_box[tid]   = ((const float4*)gb)[b*N + tid];
        s_mm[tid]    = g_maxm[b*N + tid];
        s_mi[tid]    = g_maxi[b*N + tid];
    }
    for (int j = tid; j < N*K3; j += 256) s_gp[j] = gp[(long)b*N*K3 + j];
    {
        int lc = l0 + tid; if (lc >= L) lc = L - 1;
        s_cl[tid] = g_coln[b*L + lc];
    }
    __syncthreads();

    const int l = l0 + tid;
    const int bg = bgp ? bgp[0] : 1;
    const long BL = (long)B*L;

    if (l < L) {
        const int n     = s_cl[tid];
        const int pos   = g_pos[b*L + l];
        const int crowd = s_crowd[n];

        const int lab_pre = pos ? s_lab[n] : bg;
        const int lab_fin = (crowd > 0) ? bg : lab_pre;

        float mult = 0.f;
        if (pos) {
            long idx = ((long)(b*N + n))*L + l;
            mult = __fmul_rn(__fdiv_rn(g_align[idx], __fadd_rn(s_mm[n], EPSF)), s_mi[n]);
        }
        const float cf = (crowd < 1) ? 1.f : 0.f;
        const long o = (long)b*L + l;

        out[o] = (float)lab_fin;
        ((float4*)(out + BL))[o] = s_box[n];

        const long off_sc = BL*5 + BL*(long)K*3;
        for (int cc = 0; cc < C; cc++) {
            int kept = (cc < bg) ? cc : cc + 1;
            out[off_sc + o*C + cc] = __fmul_rn((lab_pre == kept) ? mult : 0.f, cf);
        }
        const long off_gi = off_sc + BL*(long)C;
        out[off_gi + o]      = (float)(n + b*N);
        out[off_gi + BL + o] = (crowd > 0) ? 1.f : 0.f;
    }

    // coalesced pose writes for this block's 256 anchors
    float* pbase = out + BL*5 + (long)b*L*K3 + (long)l0*K3;
    const int span = min(256, L - l0) * K3;
    for (int i = tid; i < span; i += 256) {
        int ll = i / K3, j = i - ll*K3;
        pbase[i] = s_gp[s_cl[ll]*K3 + j];
    }
}

// ============================================================
extern "C" void kernel_launch(void* const* d_in, const int* in_sizes, int n_in,
                              void* d_out, int out_size)
{
    const float* ps   = (const float*)d_in[0];
    const float* pb   = (const float*)d_in[1];
    const float* pp   = (const float*)d_in[2];
    const float* ap   = (const float*)d_in[3];
    const int*   glab = (const int*)  d_in[4];
    const float* gb   = (const float*)d_in[5];
    const float* gp   = (const float*)d_in[6];
    const int*   gc   = (const int*)  d_in[7];
    const float* pad  = (const float*)d_in[8];
    const float* sg   = (const float*)d_in[9];
    const int*   bgp  = (n_in > 10) ? (const int*)d_in[10] : nullptr;

    const int K  = in_sizes[9];
    const int L  = in_sizes[3] / 2;
    const int BL = in_sizes[1] / 4;
    const int B  = BL / L;
    const int C  = in_sizes[0] / BL;
    const int N  = in_sizes[4] / B;

    dim3 blk(256);
    const int gx = (L + 255)/256;
    k0_setup  <<<B, blk>>>(gb, gp, sg, B, N, K);
    k1_metrics<<<dim3(gx, B, NCH), blk>>>(ps, pb, pp, ap, glab, gb, sg, B, L, C, N, K);
    k2_topk   <<<dim3(N, B), blk>>>(pad, B, L, N);
    k3_resolve<<<dim3(gx, B), blk>>>(B, L, N);
    k56_out   <<<dim3(gx, B), blk>>>((float*)d_out, glab, gb, gc, bgp, gp, B, L, C, N, K);
    (void)out_size;
}

// round 16
// speedup vs baseline: 1.5026x; 1.0800x over previous
#include <cuda_runtime.h>

#define EPSF 1e-9f
#define FMINN 1.17549435e-38f
#define TOPKK 13
#define MAXB 8
#define MAXN 50
#define MAXL 8400
#define MAXK 17
#define CH   25      // gts per K1 z-chunk
#define NCH  2
#define CAPC 2048    // per-gt candidate list capacity (geometric bound ~400)

extern "C" __device__ float __nv_expf(float);
extern "C" __device__ float __nv_powf(float, float);

// ---------------- device scratch ----------------
__device__ float g_align[MAXB*MAXN*MAXL];
__device__ float g_iou  [MAXB*MAXN*MAXL];
__device__ unsigned int       g_gts[NCH][MAXB*MAXL];
__device__ unsigned long long g_topk[MAXB*MAXL];
__device__ float g_cmaxv[NCH][MAXB*MAXL];
__device__ short g_cmaxi[NCH][MAXB*MAXL];
__device__ short         g_coln[MAXB*MAXL];
__device__ unsigned char g_pos [MAXB*MAXL];
__device__ float g_maxm[MAXB*MAXN];          // zero-init; k3 accumulates, k2 resets
__device__ float g_maxi[MAXB*MAXN];
__device__ int   g_ccnt[MAXB*MAXN];          // zero-init; k1 accumulates, k2 resets
__device__ float g_cv[MAXB*MAXN*CAPC];
__device__ int   g_cl[MAXB*MAXN*CAPC];

__device__ __forceinline__ float ftz(float x) { return (x < FMINN) ? 0.f : x; }

// ============================================================
// K1: per-gt setup (inlined) -> phase A (cheap screen + dense
//     zero fill) -> smem pair queue -> phase B (heavy math, FTZ)
// ============================================================
__global__ void __launch_bounds__(256)
k1_metrics(const float* __restrict__ ps, const float* __restrict__ pb,
           const float* __restrict__ pp, const float* __restrict__ ap,
           const int*   __restrict__ glab, const float* __restrict__ gb,
           const float* __restrict__ gp, const float* __restrict__ sg,
           int B, int L, int C, int N, int K)
{
    __shared__ float4 s_box[CH];
    __shared__ float4 s_kp [CH*MAXK];
    __shared__ float  s_aeps[CH], s_areac[CH], s_nvise[CH];
    __shared__ int    s_lab[CH];
    __shared__ float  s_s2[MAXK];
    __shared__ unsigned int s_bits[256];
    __shared__ unsigned long long s_amax[256];
    __shared__ unsigned int s_q[CH*256];
    __shared__ int s_qc;

    const int b = blockIdx.y, z = blockIdx.z, tid = threadIdx.x;
    const int c0 = z*CH;
    const int cn = min(N, c0 + CH) - c0;

    if (tid == 0) s_qc = 0;
    if (tid < K) { float t = __fmul_rn(2.0f, sg[tid]); s_s2[tid] = __fmul_rn(t, t); }
    if (tid < cn) {
        int n = c0 + tid;
        float4 bx = ((const float4*)gb)[b*N + n];
        s_box[tid] = bx;
        float wg = __fsub_rn(bx.z, bx.x), hg = __fsub_rn(bx.w, bx.y);
        s_areac[tid] = __fmul_rn(fmaxf(wg, 0.f), fmaxf(hg, 0.f));
        s_aeps[tid]  = __fadd_rn(__fmul_rn(__fmul_rn(wg, hg), 0.53f), EPSF);
        s_lab[tid]   = glab[b*N + n];
        float c = 0.f;
        for (int k = 0; k < K; k++) {
            float v = gp[((long)(b*N + n)*K + k)*3 + 2];
            c = __fadd_rn(c, (v > 0.f) ? 1.f : 0.f);
        }
        s_nvise[tid] = __fadd_rn(c, EPSF);
    }
    __syncthreads();
    for (int j = tid; j < cn*K; j += blockDim.x) {
        int jn = j / K, k = j - jn*K;
        const float* g = gp + ((long)(b*N + c0 + jn)*K + k)*3;
        // conservative fp32 screen: d > th => e > ~87.9 => exp < min-normal => flushed
        float th = __fmul_rn(__fmul_rn(s_s2[k], s_aeps[jn]), 175.8f);
        s_kp[j] = make_float4(g[0], g[1], th, (g[2] > 0.f) ? 1.f : 0.f);
    }
    __syncthreads();

    const int l = blockIdx.x*blockDim.x + tid;
    const bool active = (l < L);

    if (active) {
        float4 p = ((const float4*)pb)[b*L + l];
        float axx = ap[l*2], ayy = ap[l*2 + 1];
        unsigned int bits = 0;
        for (int j = 0; j < cn; j++) {
            float4 g4 = s_box[j];
            float ox = __fsub_rn(fminf(g4.z, p.z), fmaxf(g4.x, p.x));
            float oy = __fsub_rn(fminf(g4.w, p.w), fmaxf(g4.y, p.y));
            float ov = __fmul_rn(fmaxf(ox, 0.f), fmaxf(oy, 0.f));
            float dmin = fminf(fminf(__fsub_rn(axx, g4.x), __fsub_rn(ayy, g4.y)),
                               fminf(__fsub_rn(g4.z, axx), __fsub_rn(g4.w, ayy)));
            long idx = ((long)(b*N + c0 + j))*L + l;
            g_iou[idx]   = 0.f;
            g_align[idx] = 0.f;
            if (dmin > EPSF) bits |= (1u << j);
            if (ov > 0.f) {
                int qp = atomicAdd(&s_qc, 1);
                s_q[qp] = ((unsigned)tid << 5) | (unsigned)j;
            }
        }
        s_bits[tid] = bits;
        // argmax init: io2 = 0 at n = c0 (first occurrence over all-zero chunk)
        s_amax[tid] = (unsigned long long)(unsigned)(N - c0);
        g_gts[z][b*L + l] = bits;
        if (z == 0) g_topk[b*L + l] = 0ull;
    }
    __syncthreads();

    const int qc = s_qc;
    for (int q = tid; q < qc; q += 256) {
        unsigned e = s_q[q];
        int ll = (int)(e >> 5), j = (int)(e & 31);
        int lg = blockIdx.x*256 + ll;
        int n  = c0 + j;
        float4 p = ((const float4*)pb)[b*L + lg];
        float area_p = __fmul_rn(fmaxf(__fsub_rn(p.z, p.x), 0.f),
                                 fmaxf(__fsub_rn(p.w, p.y), 0.f));
        float4 g4 = s_box[j];
        float ox = __fsub_rn(fminf(g4.z, p.z), fmaxf(g4.x, p.x));
        float oy = __fsub_rn(fminf(g4.w, p.w), fmaxf(g4.y, p.y));
        float ov = __fmul_rn(fmaxf(ox, 0.f), fmaxf(oy, 0.f));
        float den = __fadd_rn(__fsub_rn(__fadd_rn(s_areac[j], area_p), ov), EPSF);
        float iou = __fdiv_rn(ov, den);
        float aeps = s_aeps[j];
        const float2* pr = (const float2*)(pp + ((long)(b*L + lg))*MAXK*2);
        float s = 0.f;
        #pragma unroll
        for (int k = 0; k < MAXK; k++) {
            float4 kk = s_kp[j*MAXK + k];
            if (kk.w > 0.f) {
                float2 q2 = pr[k];
                float dx = __fsub_rn(kk.x, q2.x);
                float dy = __fsub_rn(kk.y, q2.y);
                float d  = __fadd_rn(__fmul_rn(dx, dx), __fmul_rn(dy, dy));
                if (d <= kk.z) {
                    float e2 = __fdiv_rn(__fdiv_rn(__fdiv_rn(d, s_s2[k]), aeps), 2.0f);
                    s = __fadd_rn(s, ftz(__nv_expf(-e2)));
                }
            }
        }
        float oks = ftz(__fdiv_rn(s, s_nvise[j]));
        float io2 = ftz(__fmul_rn(iou, oks));
        float p6  = ftz(__nv_powf(io2, 6.0f));
        float al  = ftz(__fmul_rn(ps[(long)(b*L + lg)*C + s_lab[j]], p6));

        long idx = ((long)(b*N + n))*L + lg;
        g_iou[idx]   = io2;
        g_align[idx] = al;
        unsigned long long key =
            ((unsigned long long)__float_as_uint(io2) << 32) | (unsigned)(N - n);
        atomicMax(&s_amax[ll], key);
        if (al > 0.f && ((s_bits[ll] >> j) & 1u)) {
            int id = atomicAdd(&g_ccnt[b*N + n], 1);
            if (id < CAPC) {
                g_cv[(b*N + n)*CAPC + id] = al;
                g_cl[(b*N + n)*CAPC + id] = lg;
            }
        }
    }
    __syncthreads();

    if (active) {
        unsigned long long key = s_amax[tid];
        g_cmaxv[z][b*L + l] = __uint_as_float((unsigned)(key >> 32));
        g_cmaxi[z][b*L + l] = (short)(N - (int)(key & 0xffffffffull));
    }
}

// ============================================================
// K2: top-13 per (b,n) via rank counting (no serial passes)
//     order: value desc, index asc; zero-fill lowest indices.
//     Also resets g_ccnt / g_maxm / g_maxi for next replay.
// ============================================================
__global__ void __launch_bounds__(256)
k2_topk(const float* __restrict__ pad, int B, int L, int N)
{
    __shared__ float cv[CAPC];
    __shared__ int   ci[CAPC];

    const int n = blockIdx.x, b = blockIdx.y, tid = threadIdx.x;
    const int gn = b*N + n;

    const int cnt = min(g_ccnt[gn], CAPC);
    const bool pad_ok = (pad[gn] > 0.f);
    __syncthreads();                      // all reads of g_ccnt done
    if (tid == 0) { g_ccnt[gn] = 0; g_maxm[gn] = 0.f; g_maxi[gn] = 0.f; }
    if (!pad_ok) return;

    for (int i = tid; i < cnt; i += 256) {
        cv[i] = g_cv[gn*CAPC + i];
        ci[i] = g_cl[gn*CAPC + i];
    }
    __syncthreads();

    const unsigned long long nb = 1ull << n;

    if (cnt <= TOPKK) {
        if (tid < cnt) atomicOr(&g_topk[(long)b*L + ci[tid]], nb);
        if (tid == 0) {
            int fill = TOPKK - cnt;
            for (int i = 0; fill > 0; i++) {
                bool cand = false;
                for (int j = 0; j < cnt; j++) if (ci[j] == i) { cand = true; break; }
                if (!cand) { atomicOr(&g_topk[(long)b*L + i], nb); fill--; }
            }
        }
    } else {
        for (int i = tid; i < cnt; i += 256) {
            float vi = cv[i]; int ai = ci[i];
            int beats = 0;
            for (int j = 0; j < cnt; j++) {
                float vj = cv[j]; int aj = ci[j];
                beats += (vj > vi || (vj == vi && aj < ai)) ? 1 : 0;
            }
            if (beats < TOPKK) atomicOr(&g_topk[(long)b*L + ai], nb);
        }
    }
}

// ============================================================
// K3: per-anchor resolve — bit ops + 2-way chunk-argmax combine,
//     dense reads only at positives
// ============================================================
__global__ void __launch_bounds__(512)
k3_resolve(int B, int L, int N)
{
    const int l = blockIdx.x*blockDim.x + threadIdx.x;
    const int b = blockIdx.y;
    if (l >= L) return;
    const int bl = b*L + l;

    unsigned long long gts = (unsigned long long)g_gts[0][bl]
                           | ((unsigned long long)g_gts[1][bl] << CH);
    unsigned long long pos64 = gts & g_topk[bl];
    int cnt = __popcll(pos64);

    int asg = 0, pos = 0;
    if (cnt == 1) { asg = __ffsll((long long)pos64) - 1; pos = 1; }
    else if (cnt > 1) {
        float v0 = g_cmaxv[0][bl], v1 = g_cmaxv[1][bl];
        asg = (v1 > v0) ? (int)g_cmaxi[1][bl] : (int)g_cmaxi[0][bl];
        pos = 1;
    }
    g_coln[bl] = (short)asg;
    g_pos [bl] = (unsigned char)pos;
    if (pos) {
        long idx = ((long)(b*N + asg))*L + l;
        atomicMax((int*)&g_maxm[b*N + asg], __float_as_int(g_align[idx]));
        atomicMax((int*)&g_maxi[b*N + asg], __float_as_int(g_iou[idx]));
    }
}

// ============================================================
// K56: fused outputs — coalesced pose copy via smem coln staging
// layout: [labels BL][bboxes 4BL][poses 3K*BL][scores C*BL][gtidx BL][crowd BL]
// ============================================================
__global__ void __launch_bounds__(512)
k56_out(float* __restrict__ out,
        const int* __restrict__ glab, const float* __restrict__ gb,
        const int* __restrict__ gcrowd, const int* __restrict__ bgp,
        const float* __restrict__ gp,
        int B, int L, int C, int N, int K)
{
    __shared__ int    s_lab[MAXN], s_crowd[MAXN];
    __shared__ float4 s_box[MAXN];
    __shared__ float  s_mm[MAXN], s_mi[MAXN];
    __shared__ float  s_gp[MAXN*MAXK*3];
    __shared__ short  s_cl[512];

    const int b = blockIdx.y, tid = threadIdx.x;
    const int K3 = K*3;
    const int l0 = blockIdx.x*512;

    if (tid < N) {
        s_lab[tid]   = glab[b*N + tid];
        s_crowd[tid] = gcrowd[b*N + tid];
        s_box[tid]   = ((const float4*)gb)[b*N + tid];
        s_mm[tid]    = g_maxm[b*N + tid];
        s_mi[tid]    = g_maxi[b*N + tid];
    }
    for (int j = tid; j < N*K3; j += 512) s_gp[j] = gp[(long)b*N*K3 + j];
    {
        int lc = l0 + tid; if (lc >= L) lc = L - 1;
        s_cl[tid] = g_coln[b*L + lc];
    }
    __syncthreads();

    const int l = l0 + tid;
    const int bg = bgp ? bgp[0] : 1;
    const long BL = (long)B*L;

    if (l < L) {
        const int n     = s_cl[tid];
        const int pos   = g_pos[b*L + l];
        const int crowd = s_crowd[n];

        const int lab_pre = pos ? s_lab[n] : bg;
        const int lab_fin = (crowd > 0) ? bg : lab_pre;

        float mult = 0.f;
        if (pos) {
            long idx = ((long)(b*N + n))*L + l;
            mult = __fmul_rn(__fdiv_rn(g_align[idx], __fadd_rn(s_mm[n], EPSF)), s_mi[n]);
        }
        const float cf = (crowd < 1) ? 1.f : 0.f;
        const long o = (long)b*L + l;

        out[o] = (float)lab_fin;
        ((float4*)(out + BL))[o] = s_box[n];

        const long off_sc = BL*5 + BL*(long)K*3;
        for (int cc = 0; cc < C; cc++) {
            int kept = (cc < bg) ? cc : cc + 1;
            out[off_sc + o*C + cc] = __fmul_rn((lab_pre == kept) ? mult : 0.f, cf);
        }
        const long off_gi = off_sc + BL*(long)C;
        out[off_gi + o]      = (float)(n + b*N);
        out[off_gi + BL + o] = (crowd > 0) ? 1.f : 0.f;
    }

    // coalesced pose writes for this block's anchors
    float* pbase = out + BL*5 + (long)b*L*K3 + (long)l0*K3;
    const int span = min(512, L - l0) * K3;
    for (int i = tid; i < span; i += 512) {
        int ll = i / K3, j = i - ll*K3;
        pbase[i] = s_gp[s_cl[ll]*K3 + j];
    }
}

// ============================================================
extern "C" void kernel_launch(void* const* d_in, const int* in_sizes, int n_in,
                              void* d_out, int out_size)
{
    const float* ps   = (const float*)d_in[0];
    const float* pb   = (const float*)d_in[1];
    const float* pp   = (const float*)d_in[2];
    const float* ap   = (const float*)d_in[3];
    const int*   glab = (const int*)  d_in[4];
    const float* gb   = (const float*)d_in[5];
    const float* gp   = (const float*)d_in[6];
    const int*   gc   = (const int*)  d_in[7];
    const float* pad  = (const float*)d_in[8];
    const float* sg   = (const float*)d_in[9];
    const int*   bgp  = (n_in > 10) ? (const int*)d_in[10] : nullptr;

    const int K  = in_sizes[9];
    const int L  = in_sizes[3] / 2;
    const int BL = in_sizes[1] / 4;
    const int B  = BL / L;
    const int C  = in_sizes[0] / BL;
    const int N  = in_sizes[4] / B;

    const int gx = (L + 255)/256;
    const int gx5 = (L + 511)/512;
    k1_metrics<<<dim3(gx, B, NCH), 256>>>(ps, pb, pp, ap, glab, gb, gp, sg, B, L, C, N, K);
    k2_topk   <<<dim3(N, B), 256>>>(pad, B, L, N);
    k3_resolve<<<dim3(gx5, B), 512>>>(B, L, N);
    k56_out   <<<dim3(gx5, B), 512>>>((float*)d_out, glab, gb, gc, bgp, gp, B, L, C, N, K);
    (void)out_size;
}

// round 17
// speedup vs baseline: 1.5988x; 1.0640x over previous
#include <cuda_runtime.h>

#define EPSF 1e-9f
#define FMINN 1.17549435e-38f
#define TOPKK 13
#define MAXB 8
#define MAXN 50
#define MAXL 8400
#define MAXK 17
#define CH   25      // gts per K1 z-chunk
#define NCH  2
#define CAPC 2048    // per-gt candidate list capacity (geometric bound ~400)

extern "C" __device__ float __nv_expf(float);
extern "C" __device__ float __nv_powf(float, float);

// ---------------- device scratch ----------------
__device__ float g_align[MAXB*MAXN*MAXL];
__device__ float g_iou  [MAXB*MAXN*MAXL];
__device__ unsigned int       g_gts[NCH][MAXB*MAXL];
__device__ unsigned long long g_topk[MAXB*MAXL];
__device__ float g_cmaxv[NCH][MAXB*MAXL];
__device__ short g_cmaxi[NCH][MAXB*MAXL];
__device__ short         g_coln[MAXB*MAXL];
__device__ unsigned char g_pos [MAXB*MAXL];
__device__ float g_maxm[MAXB*MAXN];          // zero-init; k3 accumulates, k2 resets
__device__ float g_maxi[MAXB*MAXN];
__device__ int   g_ccnt[MAXB*MAXN];          // zero-init; k1 accumulates, k2 resets
__device__ float g_cv[MAXB*MAXN*CAPC];
__device__ int   g_cl[MAXB*MAXN*CAPC];

__device__ __forceinline__ float ftz(float x) { return (x < FMINN) ? 0.f : x; }

// ============================================================
// K1: per-gt setup (inlined) -> phase A (cheap screen + dense
//     zero fill) -> smem pair queue -> phase B (heavy math, FTZ)
// ============================================================
__global__ void __launch_bounds__(256)
k1_metrics(const float* __restrict__ ps, const float* __restrict__ pb,
           const float* __restrict__ pp, const float* __restrict__ ap,
           const int*   __restrict__ glab, const float* __restrict__ gb,
           const float* __restrict__ gp, const float* __restrict__ sg,
           int B, int L, int C, int N, int K)
{
    __shared__ float4 s_box[CH];
    __shared__ float4 s_kp [CH*MAXK];
    __shared__ float  s_aeps[CH], s_areac[CH], s_nvise[CH];
    __shared__ int    s_lab[CH];
    __shared__ float  s_s2[MAXK];
    __shared__ unsigned int s_bits[256];
    __shared__ unsigned long long s_amax[256];
    __shared__ unsigned int s_q[CH*256];
    __shared__ int s_qc;

    const int b = blockIdx.y, z = blockIdx.z, tid = threadIdx.x;
    const int c0 = z*CH;
    const int cn = min(N, c0 + CH) - c0;

    if (tid == 0) s_qc = 0;
    if (tid < K) { float t = __fmul_rn(2.0f, sg[tid]); s_s2[tid] = __fmul_rn(t, t); }
    if (tid < cn) {
        int n = c0 + tid;
        float4 bx = ((const float4*)gb)[b*N + n];
        s_box[tid] = bx;
        float wg = __fsub_rn(bx.z, bx.x), hg = __fsub_rn(bx.w, bx.y);
        s_areac[tid] = __fmul_rn(fmaxf(wg, 0.f), fmaxf(hg, 0.f));
        s_aeps[tid]  = __fadd_rn(__fmul_rn(__fmul_rn(wg, hg), 0.53f), EPSF);
        s_lab[tid]   = glab[b*N + n];
        float c = 0.f;
        for (int k = 0; k < K; k++) {
            float v = gp[((long)(b*N + n)*K + k)*3 + 2];
            c = __fadd_rn(c, (v > 0.f) ? 1.f : 0.f);
        }
        s_nvise[tid] = __fadd_rn(c, EPSF);
    }
    __syncthreads();
    for (int j = tid; j < cn*K; j += blockDim.x) {
        int jn = j / K, k = j - jn*K;
        const float* g = gp + ((long)(b*N + c0 + jn)*K + k)*3;
        // conservative fp32 screen: d > th => e > ~87.9 => exp < min-normal => flushed
        float th = __fmul_rn(__fmul_rn(s_s2[k], s_aeps[jn]), 175.8f);
        s_kp[j] = make_float4(g[0], g[1], th, (g[2] > 0.f) ? 1.f : 0.f);
    }
    __syncthreads();

    const int l = blockIdx.x*blockDim.x + tid;
    const bool active = (l < L);

    if (active) {
        float4 p = ((const float4*)pb)[b*L + l];
        float axx = ap[l*2], ayy = ap[l*2 + 1];
        unsigned int bits = 0;
        for (int j = 0; j < cn; j++) {
            float4 g4 = s_box[j];
            float ox = __fsub_rn(fminf(g4.z, p.z), fmaxf(g4.x, p.x));
            float oy = __fsub_rn(fminf(g4.w, p.w), fmaxf(g4.y, p.y));
            float ov = __fmul_rn(fmaxf(ox, 0.f), fmaxf(oy, 0.f));
            float dmin = fminf(fminf(__fsub_rn(axx, g4.x), __fsub_rn(ayy, g4.y)),
                               fminf(__fsub_rn(g4.z, axx), __fsub_rn(g4.w, ayy)));
            long idx = ((long)(b*N + c0 + j))*L + l;
            g_iou[idx]   = 0.f;
            g_align[idx] = 0.f;
            if (dmin > EPSF) bits |= (1u << j);
            if (ov > 0.f) {
                int qp = atomicAdd(&s_qc, 1);
                s_q[qp] = ((unsigned)tid << 5) | (unsigned)j;
            }
        }
        s_bits[tid] = bits;
        // argmax init: io2 = 0 at n = c0 (first occurrence over all-zero chunk)
        s_amax[tid] = (unsigned long long)(unsigned)(N - c0);
        g_gts[z][b*L + l] = bits;
        if (z == 0) g_topk[b*L + l] = 0ull;
    }
    __syncthreads();

    const int qc = s_qc;
    for (int q = tid; q < qc; q += 256) {
        unsigned e = s_q[q];
        int ll = (int)(e >> 5), j = (int)(e & 31);
        int lg = blockIdx.x*256 + ll;
        int n  = c0 + j;
        float4 p = ((const float4*)pb)[b*L + lg];
        float area_p = __fmul_rn(fmaxf(__fsub_rn(p.z, p.x), 0.f),
                                 fmaxf(__fsub_rn(p.w, p.y), 0.f));
        float4 g4 = s_box[j];
        float ox = __fsub_rn(fminf(g4.z, p.z), fmaxf(g4.x, p.x));
        float oy = __fsub_rn(fminf(g4.w, p.w), fmaxf(g4.y, p.y));
        float ov = __fmul_rn(fmaxf(ox, 0.f), fmaxf(oy, 0.f));
        float den = __fadd_rn(__fsub_rn(__fadd_rn(s_areac[j], area_p), ov), EPSF);
        float iou = __fdiv_rn(ov, den);
        float aeps = s_aeps[j];
        const float2* pr = (const float2*)(pp + ((long)(b*L + lg))*MAXK*2);
        float s = 0.f;
        #pragma unroll
        for (int k = 0; k < MAXK; k++) {
            float4 kk = s_kp[j*MAXK + k];
            if (kk.w > 0.f) {
                float2 q2 = pr[k];
                float dx = __fsub_rn(kk.x, q2.x);
                float dy = __fsub_rn(kk.y, q2.y);
                float d  = __fadd_rn(__fmul_rn(dx, dx), __fmul_rn(dy, dy));
                if (d <= kk.z) {
                    float e2 = __fdiv_rn(__fdiv_rn(__fdiv_rn(d, s_s2[k]), aeps), 2.0f);
                    s = __fadd_rn(s, ftz(__nv_expf(-e2)));
                }
            }
        }
        float oks = ftz(__fdiv_rn(s, s_nvise[j]));
        float io2 = ftz(__fmul_rn(iou, oks));
        float p6  = ftz(__nv_powf(io2, 6.0f));
        float al  = ftz(__fmul_rn(ps[(long)(b*L + lg)*C + s_lab[j]], p6));

        long idx = ((long)(b*N + n))*L + lg;
        g_iou[idx]   = io2;
        g_align[idx] = al;
        unsigned long long key =
            ((unsigned long long)__float_as_uint(io2) << 32) | (unsigned)(N - n);
        atomicMax(&s_amax[ll], key);
        if (al > 0.f && ((s_bits[ll] >> j) & 1u)) {
            int id = atomicAdd(&g_ccnt[b*N + n], 1);
            if (id < CAPC) {
                g_cv[(b*N + n)*CAPC + id] = al;
                g_cl[(b*N + n)*CAPC + id] = lg;
            }
        }
    }
    __syncthreads();

    if (active) {
        unsigned long long key = s_amax[tid];
        g_cmaxv[z][b*L + l] = __uint_as_float((unsigned)(key >> 32));
        g_cmaxi[z][b*L + l] = (short)(N - (int)(key & 0xffffffffull));
    }
}

// ============================================================
// K2: top-13 per (b,n) via rank counting; resets counters
// ============================================================
__global__ void __launch_bounds__(256)
k2_topk(const float* __restrict__ pad, int B, int L, int N)
{
    __shared__ float cv[CAPC];
    __shared__ int   ci[CAPC];

    const int n = blockIdx.x, b = blockIdx.y, tid = threadIdx.x;
    const int gn = b*N + n;

    const int cnt = min(g_ccnt[gn], CAPC);
    const bool pad_ok = (pad[gn] > 0.f);
    __syncthreads();
    if (tid == 0) { g_ccnt[gn] = 0; g_maxm[gn] = 0.f; g_maxi[gn] = 0.f; }
    if (!pad_ok) return;

    for (int i = tid; i < cnt; i += 256) {
        cv[i] = g_cv[gn*CAPC + i];
        ci[i] = g_cl[gn*CAPC + i];
    }
    __syncthreads();

    const unsigned long long nb = 1ull << n;

    if (cnt <= TOPKK) {
        if (tid < cnt) atomicOr(&g_topk[(long)b*L + ci[tid]], nb);
        if (tid == 0) {
            int fill = TOPKK - cnt;
            for (int i = 0; fill > 0; i++) {
                bool cand = false;
                for (int j = 0; j < cnt; j++) if (ci[j] == i) { cand = true; break; }
                if (!cand) { atomicOr(&g_topk[(long)b*L + i], nb); fill--; }
            }
        }
    } else {
        for (int i = tid; i < cnt; i += 256) {
            float vi = cv[i]; int ai = ci[i];
            int beats = 0;
            for (int j = 0; j < cnt; j++) {
                float vj = cv[j]; int aj = ci[j];
                beats += (vj > vi || (vj == vi && aj < ai)) ? 1 : 0;
            }
            if (beats < TOPKK) atomicOr(&g_topk[(long)b*L + ai], nb);
        }
    }
}

// ============================================================
// K3: per-anchor resolve — bit ops + 2-way chunk-argmax combine
// ============================================================
__global__ void __launch_bounds__(512)
k3_resolve(int B, int L, int N)
{
    const int l = blockIdx.x*blockDim.x + threadIdx.x;
    const int b = blockIdx.y;
    if (l >= L) return;
    const int bl = b*L + l;

    unsigned long long gts = (unsigned long long)g_gts[0][bl]
                           | ((unsigned long long)g_gts[1][bl] << CH);
    unsigned long long pos64 = gts & g_topk[bl];
    int cnt = __popcll(pos64);

    int asg = 0, pos = 0;
    if (cnt == 1) { asg = __ffsll((long long)pos64) - 1; pos = 1; }
    else if (cnt > 1) {
        float v0 = g_cmaxv[0][bl], v1 = g_cmaxv[1][bl];
        asg = (v1 > v0) ? (int)g_cmaxi[1][bl] : (int)g_cmaxi[0][bl];
        pos = 1;
    }
    g_coln[bl] = (short)asg;
    g_pos [bl] = (unsigned char)pos;
    if (pos) {
        long idx = ((long)(b*N + asg))*L + l;
        atomicMax((int*)&g_maxm[b*N + asg], __float_as_int(g_align[idx]));
        atomicMax((int*)&g_maxi[b*N + asg], __float_as_int(g_iou[idx]));
    }
}

// ============================================================
// K56: fused outputs — pose copy with constant-div + float4 stores
// layout: [labels BL][bboxes 4BL][poses 3K*BL][scores C*BL][gtidx BL][crowd BL]
// ============================================================
__global__ void __launch_bounds__(512)
k56_out(float* __restrict__ out,
        const int* __restrict__ glab, const float* __restrict__ gb,
        const int* __restrict__ gcrowd, const int* __restrict__ bgp,
        const float* __restrict__ gp,
        int B, int L, int C, int N, int K)
{
    __shared__ int    s_lab[MAXN], s_crowd[MAXN];
    __shared__ float4 s_box[MAXN];
    __shared__ float  s_mm[MAXN], s_mi[MAXN];
    __shared__ float  s_gp[MAXN*MAXK*3];
    __shared__ short  s_cl[512];

    const int b = blockIdx.y, tid = threadIdx.x;
    const int K3 = K*3;
    const int l0 = blockIdx.x*512;

    if (tid < N) {
        s_lab[tid]   = glab[b*N + tid];
        s_crowd[tid] = gcrowd[b*N + tid];
        s_box[tid]   = ((const float4*)gb)[b*N + tid];
        s_mm[tid]    = g_maxm[b*N + tid];
        s_mi[tid]    = g_maxi[b*N + tid];
    }
    for (int j = tid; j < N*K3; j += 512) s_gp[j] = gp[(long)b*N*K3 + j];
    {
        int lc = l0 + tid; if (lc >= L) lc = L - 1;
        s_cl[tid] = g_coln[b*L + lc];
    }
    __syncthreads();

    const int l = l0 + tid;
    const int bg = bgp ? bgp[0] : 1;
    const long BL = (long)B*L;

    if (l < L) {
        const int n     = s_cl[tid];
        const int pos   = g_pos[b*L + l];
        const int crowd = s_crowd[n];

        const int lab_pre = pos ? s_lab[n] : bg;
        const int lab_fin = (crowd > 0) ? bg : lab_pre;

        float mult = 0.f;
        if (pos) {
            long idx = ((long)(b*N + n))*L + l;
            mult = __fmul_rn(__fdiv_rn(g_align[idx], __fadd_rn(s_mm[n], EPSF)), s_mi[n]);
        }
        const float cf = (crowd < 1) ? 1.f : 0.f;
        const long o = (long)b*L + l;

        out[o] = (float)lab_fin;
        ((float4*)(out + BL))[o] = s_box[n];

        const long off_sc = BL*5 + BL*(long)K*3;
        for (int cc = 0; cc < C; cc++) {
            int kept = (cc < bg) ? cc : cc + 1;
            out[off_sc + o*C + cc] = __fmul_rn((lab_pre == kept) ? mult : 0.f, cf);
        }
        const long off_gi = off_sc + BL*(long)C;
        out[off_gi + o]      = (float)(n + b*N);
        out[off_gi + BL + o] = (crowd > 0) ? 1.f : 0.f;
    }

    // coalesced pose writes for this block's anchors
    float* pbase = out + BL*5 + (long)b*L*K3 + (long)l0*K3;
    const int nanch = min(512, L - l0);
    if (K3 == 51 && (nanch & 3) == 0) {
        // specialized: constant division, one div per 4 elements, float4 stores
        float4* p4 = (float4*)pbase;
        const int span4 = (nanch * 51) >> 2;
        for (int i4 = tid; i4 < span4; i4 += 512) {
            unsigned i = (unsigned)i4 << 2;
            unsigned ll = i / 51u;            // constant div -> mulhi+shift
            unsigned j  = i - ll*51u;
            int base = (int)s_cl[ll] * 51;
            float v[4];
            #pragma unroll
            for (int t = 0; t < 4; t++) {
                v[t] = s_gp[base + (int)j];
                if (++j == 51u) { j = 0u; ll++; base = (int)s_cl[ll] * 51; }
            }
            p4[i4] = make_float4(v[0], v[1], v[2], v[3]);
        }
    } else {
        const int span = nanch * K3;
        for (int i = tid; i < span; i += 512) {
            int ll = i / K3, j = i - ll*K3;
            pbase[i] = s_gp[s_cl[ll]*K3 + j];
        }
    }
}

// ============================================================
extern "C" void kernel_launch(void* const* d_in, const int* in_sizes, int n_in,
                              void* d_out, int out_size)
{
    const float* ps   = (const float*)d_in[0];
    const float* pb   = (const float*)d_in[1];
    const float* pp   = (const float*)d_in[2];
    const float* ap   = (const float*)d_in[3];
    const int*   glab = (const int*)  d_in[4];
    const float* gb   = (const float*)d_in[5];
    const float* gp   = (const float*)d_in[6];
    const int*   gc   = (const int*)  d_in[7];
    const float* pad  = (const float*)d_in[8];
    const float* sg   = (const float*)d_in[9];
    const int*   bgp  = (n_in > 10) ? (const int*)d_in[10] : nullptr;

    const int K  = in_sizes[9];
    const int L  = in_sizes[3] / 2;
    const int BL = in_sizes[1] / 4;
    const int B  = BL / L;
    const int C  = in_sizes[0] / BL;
    const int N  = in_sizes[4] / B;

    const int gx  = (L + 255)/256;
    const int gx5 = (L + 511)/512;
    k1_metrics<<<dim3(gx, B, NCH), 256>>>(ps, pb, pp, ap, glab, gb, gp, sg, B, L, C, N, K);
    k2_topk   <<<dim3(N, B), 256>>>(pad, B, L, N);
    k3_resolve<<<dim3(gx5, B), 512>>>(B, L, N);
    k56_out   <<<dim3(gx5, B), 512>>>((float*)d_out, glab, gb, gc, bgp, gp, B, L, C, N, K);
    (void)out_size;
}